// round 11
// baseline (speedup 1.0000x reference)
#include <cuda_runtime.h>

#define LBL 32
#define WPB 8
#define ESTR 36   // E^T staging stride (floats): conflict-free STS + B-frag LDS

typedef unsigned int u32;

// Static device scratch (allocation-free). Distinct buffer per phase.
// All score buffers use ROTATED rows: element for label l of row n lives at
// column (l + 8*(n%4)) % 32 -> both the mma D-fragment scatter-store and the
// next level's lane-per-label load are bank-conflict-free.
__device__ __align__(16) float g_bufA[16384 * LBL];
__device__ __align__(16) float g_bufB[2048 * LBL];
__device__ __align__(16) float g_bufC[256 * LBL];
__device__ __align__(16) float g_bufD[32 * LBL];

// Grid barrier state (re-entrant across graph replays).
__device__ unsigned g_bar_count = 0;
__device__ unsigned g_bar_phase = 0;

__device__ __forceinline__ void grid_barrier(unsigned nblocks, unsigned& myphase) {
    __syncthreads();
    if (threadIdx.x == 0) {
        __threadfence();
        unsigned arr = atomicAdd(&g_bar_count, 1u);
        if (arr == nblocks - 1u) {
            g_bar_count = 0;
            __threadfence();
            atomicAdd(&g_bar_phase, 1u);
        } else {
            while (*(volatile unsigned*)&g_bar_phase == myphase)
                __nanosleep(64);
        }
    }
    __syncthreads();
    myphase++;
}

// Warp max of f32 via monotone int map + redux.sync.max.s32 (1 instruction).
__device__ __forceinline__ float warp_fmax1(float x) {
    int b = __float_as_int(x);
    int key = b ^ ((b >> 31) & 0x7fffffff);
    int r;
    asm("redux.sync.max.s32 %0, %1, 0xffffffff;" : "=r"(r) : "r"(key));
    return __int_as_float(r ^ ((r >> 31) & 0x7fffffff));
}

__device__ __forceinline__ u32 f2tf32(float x) {
    u32 h; asm("cvt.rna.tf32.f32 %0, %1;" : "=r"(h) : "f"(x)); return h;
}

// D(16x8) += A(16x8,tf32,row) @ B(8x8,tf32,col), fp32 accumulate.
__device__ __forceinline__ void mma_acc(float c[4], const u32 a[4], u32 b0, u32 b1) {
    asm("mma.sync.aligned.m16n8k8.row.col.f32.tf32.tf32.f32 "
        "{%0,%1,%2,%3}, {%4,%5,%6,%7}, {%8,%9}, {%0,%1,%2,%3};"
        : "+f"(c[0]), "+f"(c[1]), "+f"(c[2]), "+f"(c[3])
        : "r"(a[0]), "r"(a[1]), "r"(a[2]), "r"(a[3]), "r"(b0), "r"(b1));
}

// ---------------------------------------------------------------------------
// Batch of 4 tree nodes per warp via tensor cores.
//   D[label][2i+0] = dot(expT[label,:], exp(left_i  - ml_i))
//   D[label][2i+1] = dot(expT[label,:], exp(right_i - mr_i))
//   res = em + ml + mr + log(dL*dR)
// Thread t gets node (t%4) and labels (t/4) + 8k, k=0..3, in res[k].
// Full tf32x2 4-term split (AhBh + AhBl + AlBh + AlBl) ~ fp32 accuracy.
// Staging stg[vec][label] is LABEL-indexed (store at +lane; stride-1,
// conflict-free). The rotated child read uses a permuted column il, also
// conflict-free.
// ---------------------------------------------------------------------------
template<bool ROT_IN>
__device__ __forceinline__ void batch4(
    const float* __restrict__ child, int crow0,   // child rows crow0..crow0+7
    const float* __restrict__ em,    int erow0,   // emission rows erow0..+3
    int lane, float* __restrict__ stg,            // 8*ESTR floats per warp
    const u32 (&AH)[2][4][4], const u32 (&AL)[2][4][4],
    float res[4])
{
    const int tq = lane & 3, tg = lane >> 2;

    float mm0, mm1, mm2, mm3;
    #pragma unroll
    for (int i = 0; i < 4; i++) {
        int rl = crow0 + 2 * i, rr = rl + 1;
        int il = ROT_IN ? ((lane + 8 * rl) & 31) : lane;  // column of label `lane`
        int ir = ROT_IN ? ((lane + 8 * rr) & 31) : lane;
        float lv = child[rl * LBL + il];   // value of label `lane`
        float rv = child[rr * LBL + ir];
        float ml = warp_fmax1(lv);
        float mr = warp_fmax1(rv);
        stg[(2 * i) * ESTR + lane]     = __expf(lv - ml);   // E^T[vec][label]
        stg[(2 * i + 1) * ESTR + lane] = __expf(rv - mr);
        float s = ml + mr;
        if (i == 0) mm0 = s; else if (i == 1) mm1 = s;
        else if (i == 2) mm2 = s; else mm3 = s;
    }
    // emissions for (node=erow0+tq, label=tg+8k) — issue early
    float emv[4];
    #pragma unroll
    for (int k = 0; k < 4; k++)
        emv[k] = em[(erow0 + tq) * LBL + tg + 8 * k];
    __syncwarp();

    float c0[4] = {0.f, 0.f, 0.f, 0.f};   // labels tg, tg+8
    float c1[4] = {0.f, 0.f, 0.f, 0.f};   // labels tg+16, tg+24
    #pragma unroll
    for (int s = 0; s < 4; s++) {
        // B frag: b0 = E[k=tq+8s][n=tg], b1 = E[k=tq+4+8s][n=tg]
        float b0f = stg[tg * ESTR + tq + 8 * s];
        float b1f = stg[tg * ESTR + tq + 4 + 8 * s];
        u32 b0h = f2tf32(b0f), b1h = f2tf32(b1f);
        u32 b0l = f2tf32(b0f - __uint_as_float(b0h));
        u32 b1l = f2tf32(b1f - __uint_as_float(b1h));
        mma_acc(c0, AH[0][s], b0h, b1h);
        mma_acc(c1, AH[1][s], b0h, b1h);
        mma_acc(c0, AH[0][s], b0l, b1l);
        mma_acc(c1, AH[1][s], b0l, b1l);
        mma_acc(c0, AL[0][s], b0h, b1h);
        mma_acc(c1, AL[1][s], b0h, b1h);
        mma_acc(c0, AL[0][s], b0l, b1l);
        mma_acc(c1, AL[1][s], b0l, b1l);
    }
    __syncwarp();   // stg safe to reuse by next call

    float mmq = (tq & 2) ? ((tq & 1) ? mm3 : mm2) : ((tq & 1) ? mm1 : mm0);
    res[0] = emv[0] + mmq + __logf(c0[0] * c0[1]);
    res[1] = emv[1] + mmq + __logf(c0[2] * c0[3]);
    res[2] = emv[2] + mmq + __logf(c1[0] * c1[1]);
    res[3] = emv[3] + mmq + __logf(c1[2] * c1[3]);
}

// ---------------------------------------------------------------------------
// Persistent kernel: all levels in one launch, grid barrier between fused-3
// groups. Slab = 32 nodes at level V -> 16 -> 8 through shared memory.
// ---------------------------------------------------------------------------
__global__ void __launch_bounds__(WPB * 32, 2)
persistent_kernel(const float* __restrict__ emissions,
                  const float* __restrict__ trans,
                  float* __restrict__ d_out,
                  int n_leaves)
{
    __shared__ __align__(16) float s1[32 * LBL];
    __shared__ __align__(16) float s2[16 * LBL];
    __shared__ __align__(16) float stg[WPB][8 * ESTR];

    int lane = threadIdx.x & 31;
    int w    = threadIdx.x >> 5;
    const int tq = lane & 3, tg = lane >> 2;
    unsigned nblocks = gridDim.x;
    unsigned myphase = *(volatile unsigned*)&g_bar_phase;

    // A fragments of expT = exp(trans): hi/lo tf32 split, 64 regs, once.
    u32 AH[2][4][4], AL[2][4][4];
    #pragma unroll
    for (int r = 0; r < 2; r++) {
        #pragma unroll
        for (int s = 0; s < 4; s++) {
            int r0 = tg + 16 * r, r1 = r0 + 8;
            int ca = tq + 8 * s,  cb = ca + 4;
            float v0 = __expf(trans[r0 * LBL + ca]);
            float v1 = __expf(trans[r1 * LBL + ca]);
            float v2 = __expf(trans[r0 * LBL + cb]);
            float v3 = __expf(trans[r1 * LBL + cb]);
            AH[r][s][0] = f2tf32(v0); AL[r][s][0] = f2tf32(v0 - __uint_as_float(AH[r][s][0]));
            AH[r][s][1] = f2tf32(v1); AL[r][s][1] = f2tf32(v1 - __uint_as_float(AH[r][s][1]));
            AH[r][s][2] = f2tf32(v2); AL[r][s][2] = f2tf32(v2 - __uint_as_float(AH[r][s][2]));
            AH[r][s][3] = f2tf32(v3); AL[r][s][3] = f2tf32(v3 - __uint_as_float(AH[r][s][3]));
        }
    }

    float* bufs[4] = { g_bufA, g_bufB, g_bufC, g_bufD };
    const float* child = emissions + (size_t)(n_leaves - 1) * LBL;  // leaves (unrotated)

    int V = n_leaves / 2;
    int gi = 0;
    while (V >= 128) {
        float* out = bufs[gi];
        const float* em1 = emissions + (size_t)(V - 1) * LBL;
        const float* em2 = emissions + (size_t)(V / 2 - 1) * LBL;
        const float* em3 = emissions + (size_t)(V / 4 - 1) * LBL;
        int nslabs = V / 32;

        for (int s = blockIdx.x; s < nslabs; s += nblocks) {
            float res[4];
            // ---- Stage 1: 32 nodes, 8 warps x 4 nodes. Leaves unrotated.
            {
                int g0 = s * 32 + 4 * w;
                if (gi == 0)
                    batch4<false>(child, 2 * g0, em1, g0, lane, stg[w], AH, AL, res);
                else
                    batch4<true >(child, 2 * g0, em1, g0, lane, stg[w], AH, AL, res);
                #pragma unroll
                for (int k = 0; k < 4; k++)
                    s1[(4 * w + tq) * LBL + ((tg + 8 * k + 8 * tq) & 31)] = res[k];
            }
            __syncthreads();

            // ---- Stage 2: 16 nodes, warps 0-3.
            if (w < 4) {
                batch4<true>(s1, 8 * w, em2, s * 16 + 4 * w, lane, stg[w], AH, AL, res);
                #pragma unroll
                for (int k = 0; k < 4; k++)
                    s2[(4 * w + tq) * LBL + ((tg + 8 * k + 8 * tq) & 31)] = res[k];
            }
            __syncthreads();

            // ---- Stage 3: 8 nodes, warps 0-1 -> global (rotated).
            if (w < 2) {
                batch4<true>(s2, 8 * w, em3, s * 8 + 4 * w, lane, stg[w], AH, AL, res);
                int row = s * 8 + 4 * w + tq;
                #pragma unroll
                for (int k = 0; k < 4; k++)
                    out[(size_t)row * LBL + ((tg + 8 * k + 8 * (row & 3)) & 31)] = res[k];
            }
            __syncthreads();
        }

        grid_barrier(nblocks, myphase);
        child = out;
        V >>= 3;
        gi++;
    }

    // ---- Tail: levels V..1 (V=16 for 131072 leaves), block 0 only.
    // Pad nodes (v<4) read in-bounds stale rows (finite; exp(x-max)<=1, so
    // no inf/nan) and are not stored.
    if (blockIdx.x == 0) {
        const float* c = child;   // g_bufD, 32 rotated rows
        float* o = s2;
        for (int v = V; v >= 1; v >>= 1) {
            const float* em = emissions + (size_t)(v - 1) * LBL;
            int aw = (v >= 4) ? (v / 4) : 1;
            if (w < aw) {
                float res[4];
                batch4<true>(c, 8 * w, em, 4 * w, lane, stg[w], AH, AL, res);
                int valid = v - 4 * w; if (valid > 4) valid = 4;
                if (v == 1) {
                    if (tq == 0) {
                        #pragma unroll
                        for (int k = 0; k < 4; k++)
                            d_out[tg + 8 * k] = res[k];
                    }
                } else {
                    #pragma unroll
                    for (int k = 0; k < 4; k++)
                        if (tq < valid)
                            o[(4 * w + tq) * LBL + ((tg + 8 * k + 8 * tq) & 31)] = res[k];
                }
            }
            __syncthreads();
            c = o;
            o = (o == s2) ? s1 : s2;
        }
    }
}

// ---------------------------------------------------------------------------
// One graph node. Grid sized so ALL blocks are simultaneously resident.
// ---------------------------------------------------------------------------
extern "C" void kernel_launch(void* const* d_in, const int* in_sizes, int n_in,
                              void* d_out, int out_size)
{
    const float* emissions = (const float*)d_in[0];
    const float* trans     = (const float*)d_in[1];
    float* out = (float*)d_out;

    int n_nodes  = in_sizes[0] / LBL;
    int n_leaves = (n_nodes + 1) / 2;

    static int grid = 0;
    if (grid == 0) {
        int dev = 0, sms = 0, perSM = 0;
        cudaGetDevice(&dev);
        cudaDeviceGetAttribute(&sms, cudaDevAttrMultiProcessorCount, dev);
        cudaOccupancyMaxActiveBlocksPerMultiprocessor(
            &perSM, persistent_kernel, WPB * 32, 0);
        if (perSM < 1) perSM = 1;
        grid = sms * perSM;
        int maxSlabs = (n_leaves / 2) / 32;
        if (grid > maxSlabs) grid = maxSlabs;
        if (grid < 1) grid = 1;
    }

    persistent_kernel<<<grid, WPB * 32>>>(emissions, trans, out, n_leaves);
}

// round 12
// speedup vs baseline: 1.0118x; 1.0118x over previous
#include <cuda_runtime.h>

#define LBL 32
#define WPB 8
#define ESTR 36   // E^T staging stride (floats): conflict-free STS + B-frag LDS

typedef unsigned int u32;

// Static device scratch (allocation-free). Distinct buffer per phase.
// All score buffers use ROTATED rows: element for label l of row n lives at
// column (l + 8*(n%4)) % 32 -> mma D-fragment scatter-store and the next
// level's lane-per-label load are both bank-conflict-free.
__device__ __align__(16) float g_bufA[16384 * LBL];
__device__ __align__(16) float g_bufB[2048 * LBL];
__device__ __align__(16) float g_bufC[256 * LBL];
__device__ __align__(16) float g_bufD[32 * LBL];

// Grid barrier state (re-entrant across graph replays).
__device__ unsigned g_bar_count = 0;
__device__ unsigned g_bar_phase = 0;

__device__ __forceinline__ void grid_barrier(unsigned nblocks, unsigned& myphase) {
    __syncthreads();
    if (threadIdx.x == 0) {
        __threadfence();
        unsigned arr = atomicAdd(&g_bar_count, 1u);
        if (arr == nblocks - 1u) {
            g_bar_count = 0;
            __threadfence();
            atomicAdd(&g_bar_phase, 1u);
        } else {
            while (*(volatile unsigned*)&g_bar_phase == myphase)
                __nanosleep(64);
        }
    }
    __syncthreads();
    myphase++;
}

// Warp max of f32 via monotone int map + redux.sync.max.s32 (1 instruction).
__device__ __forceinline__ float warp_fmax1(float x) {
    int b = __float_as_int(x);
    int key = b ^ ((b >> 31) & 0x7fffffff);
    int r;
    asm("redux.sync.max.s32 %0, %1, 0xffffffff;" : "=r"(r) : "r"(key));
    return __int_as_float(r ^ ((r >> 31) & 0x7fffffff));
}

__device__ __forceinline__ u32 f2tf32(float x) {
    u32 h; asm("cvt.rna.tf32.f32 %0, %1;" : "=r"(h) : "f"(x)); return h;
}

// D(16x8) += A(16x8,tf32,row) @ B(8x8,tf32,col), fp32 accumulate.
__device__ __forceinline__ void mma_acc(float c[4], const u32 a[4], u32 b0, u32 b1) {
    asm("mma.sync.aligned.m16n8k8.row.col.f32.tf32.tf32.f32 "
        "{%0,%1,%2,%3}, {%4,%5,%6,%7}, {%8,%9}, {%0,%1,%2,%3};"
        : "+f"(c[0]), "+f"(c[1]), "+f"(c[2]), "+f"(c[3])
        : "r"(a[0]), "r"(a[1]), "r"(a[2]), "r"(a[3]), "r"(b0), "r"(b1));
}

// ---------------------------------------------------------------------------
// Batch of 4 tree nodes per warp via tensor cores.
//   D[label][2i+0] = dot(expT[label,:], exp(left_i  - ml_i))
//   D[label][2i+1] = dot(expT[label,:], exp(right_i - mr_i))
//   res = em + ml + mr + log(dL*dR)
// Thread t owns node (t%4) and labels (t/4)+8k in res[k].
// 3-term tf32x2 split (AhBh + AhBl + AlBh); residual ~2^-22 per dot.
// Staging stg[vec][label] is LABEL-indexed (store at +lane, stride-1).
// ---------------------------------------------------------------------------
template<bool ROT_IN>
__device__ __forceinline__ void batch4(
    const float* __restrict__ child, int crow0,   // child rows crow0..crow0+7
    const float* __restrict__ em,    int erow0,   // emission rows erow0..+3
    int lane, float* __restrict__ stg,            // 8*ESTR floats per warp
    const u32 (&AH)[2][4][4], const u32 (&AL)[2][4][4],
    float res[4])
{
    const int tq = lane & 3, tg = lane >> 2;

    float mm0, mm1, mm2, mm3;
    #pragma unroll
    for (int i = 0; i < 4; i++) {
        int rl = crow0 + 2 * i, rr = rl + 1;
        int il = ROT_IN ? ((lane + 8 * rl) & 31) : lane;  // column of label `lane`
        int ir = ROT_IN ? ((lane + 8 * rr) & 31) : lane;
        float lv = child[rl * LBL + il];
        float rv = child[rr * LBL + ir];
        float ml = warp_fmax1(lv);
        float mr = warp_fmax1(rv);
        stg[(2 * i) * ESTR + lane]     = __expf(lv - ml);   // E^T[vec][label]
        stg[(2 * i + 1) * ESTR + lane] = __expf(rv - mr);
        float s = ml + mr;
        if (i == 0) mm0 = s; else if (i == 1) mm1 = s;
        else if (i == 2) mm2 = s; else mm3 = s;
    }
    float emv[4];
    #pragma unroll
    for (int k = 0; k < 4; k++)
        emv[k] = em[(erow0 + tq) * LBL + tg + 8 * k];
    __syncwarp();

    float c0[4] = {0.f, 0.f, 0.f, 0.f};   // labels tg, tg+8
    float c1[4] = {0.f, 0.f, 0.f, 0.f};   // labels tg+16, tg+24
    #pragma unroll
    for (int s = 0; s < 4; s++) {
        float b0f = stg[tg * ESTR + tq + 8 * s];
        float b1f = stg[tg * ESTR + tq + 4 + 8 * s];
        u32 b0h = f2tf32(b0f), b1h = f2tf32(b1f);
        u32 b0l = f2tf32(b0f - __uint_as_float(b0h));
        u32 b1l = f2tf32(b1f - __uint_as_float(b1h));
        mma_acc(c0, AH[0][s], b0h, b1h);
        mma_acc(c1, AH[1][s], b0h, b1h);
        mma_acc(c0, AH[0][s], b0l, b1l);
        mma_acc(c1, AH[1][s], b0l, b1l);
        mma_acc(c0, AL[0][s], b0h, b1h);
        mma_acc(c1, AL[1][s], b0h, b1h);
    }
    __syncwarp();   // stg safe to reuse by next call

    float mmq = (tq & 2) ? ((tq & 1) ? mm3 : mm2) : ((tq & 1) ? mm1 : mm0);
    res[0] = emv[0] + mmq + __logf(c0[0] * c0[1]);
    res[1] = emv[1] + mmq + __logf(c0[2] * c0[3]);
    res[2] = emv[2] + mmq + __logf(c1[0] * c1[1]);
    res[3] = emv[3] + mmq + __logf(c1[2] * c1[3]);
}

// ---------------------------------------------------------------------------
// Persistent kernel. Slab = 64 nodes at level V -> 32 -> 16 through shared
// memory (stage1: 2 batches/warp; stage2: all 8 warps; stage3: 4 warps).
// ---------------------------------------------------------------------------
__global__ void __launch_bounds__(WPB * 32, 2)
persistent_kernel(const float* __restrict__ emissions,
                  const float* __restrict__ trans,
                  float* __restrict__ d_out,
                  int n_leaves)
{
    __shared__ __align__(16) float s1[64 * LBL];
    __shared__ __align__(16) float s2[32 * LBL];
    __shared__ __align__(16) float stg[WPB][8 * ESTR];

    int lane = threadIdx.x & 31;
    int w    = threadIdx.x >> 5;
    const int tq = lane & 3, tg = lane >> 2;
    unsigned nblocks = gridDim.x;
    unsigned myphase = *(volatile unsigned*)&g_bar_phase;

    // A fragments of expT = exp(trans): hi/lo tf32 split, 64 regs, once.
    u32 AH[2][4][4], AL[2][4][4];
    #pragma unroll
    for (int r = 0; r < 2; r++) {
        #pragma unroll
        for (int s = 0; s < 4; s++) {
            int r0 = tg + 16 * r, r1 = r0 + 8;
            int ca = tq + 8 * s,  cb = ca + 4;
            float v0 = __expf(trans[r0 * LBL + ca]);
            float v1 = __expf(trans[r1 * LBL + ca]);
            float v2 = __expf(trans[r0 * LBL + cb]);
            float v3 = __expf(trans[r1 * LBL + cb]);
            AH[r][s][0] = f2tf32(v0); AL[r][s][0] = f2tf32(v0 - __uint_as_float(AH[r][s][0]));
            AH[r][s][1] = f2tf32(v1); AL[r][s][1] = f2tf32(v1 - __uint_as_float(AH[r][s][1]));
            AH[r][s][2] = f2tf32(v2); AL[r][s][2] = f2tf32(v2 - __uint_as_float(AH[r][s][2]));
            AH[r][s][3] = f2tf32(v3); AL[r][s][3] = f2tf32(v3 - __uint_as_float(AH[r][s][3]));
        }
    }

    float* bufs[4] = { g_bufA, g_bufB, g_bufC, g_bufD };
    const float* child = emissions + (size_t)(n_leaves - 1) * LBL;  // leaves (unrotated)

    int V = n_leaves / 2;
    int gi = 0;
    while (V >= 128) {
        float* out = bufs[gi];
        const float* em1 = emissions + (size_t)(V - 1) * LBL;
        const float* em2 = emissions + (size_t)(V / 2 - 1) * LBL;
        const float* em3 = emissions + (size_t)(V / 4 - 1) * LBL;
        int nslabs = V / 64;

        for (int s = blockIdx.x; s < nslabs; s += nblocks) {
            float res0[4], res1[4];
            // ---- Stage 1: 64 nodes at level V, 2 batches per warp.
            {
                int g0 = s * 64 + 4 * w;            // batch b = w
                int g1 = s * 64 + 4 * (w + 8);      // batch b = w+8
                if (gi == 0) {
                    batch4<false>(child, 2 * g0, em1, g0, lane, stg[w], AH, AL, res0);
                    batch4<false>(child, 2 * g1, em1, g1, lane, stg[w], AH, AL, res1);
                } else {
                    batch4<true >(child, 2 * g0, em1, g0, lane, stg[w], AH, AL, res0);
                    batch4<true >(child, 2 * g1, em1, g1, lane, stg[w], AH, AL, res1);
                }
                #pragma unroll
                for (int k = 0; k < 4; k++) {
                    s1[(4 * w + tq) * LBL + ((tg + 8 * k + 8 * tq) & 31)] = res0[k];
                    s1[(4 * (w + 8) + tq) * LBL + ((tg + 8 * k + 8 * tq) & 31)] = res1[k];
                }
            }
            __syncthreads();

            // ---- Stage 2: 32 nodes at level V/2, all 8 warps.
            {
                batch4<true>(s1, 8 * w, em2, s * 32 + 4 * w, lane, stg[w], AH, AL, res0);
                #pragma unroll
                for (int k = 0; k < 4; k++)
                    s2[(4 * w + tq) * LBL + ((tg + 8 * k + 8 * tq) & 31)] = res0[k];
            }
            __syncthreads();

            // ---- Stage 3: 16 nodes at level V/4, warps 0-3 -> global (rotated).
            if (w < 4) {
                batch4<true>(s2, 8 * w, em3, s * 16 + 4 * w, lane, stg[w], AH, AL, res0);
                int row = s * 16 + 4 * w + tq;
                #pragma unroll
                for (int k = 0; k < 4; k++)
                    out[(size_t)row * LBL + ((tg + 8 * k + 8 * (row & 3)) & 31)] = res0[k];
            }
            __syncthreads();
        }

        grid_barrier(nblocks, myphase);
        child = out;
        V >>= 3;
        gi++;
    }

    // ---- Tail: levels V..1 (V=16 for 131072 leaves), block 0 only.
    // Pad nodes (v<4) read in-bounds stale rows (finite) and are not stored.
    if (blockIdx.x == 0) {
        const float* c = child;   // g_bufD, 32 rotated rows
        float* o = s2;
        for (int v = V; v >= 1; v >>= 1) {
            const float* em = emissions + (size_t)(v - 1) * LBL;
            int aw = (v >= 4) ? (v / 4) : 1;
            if (w < aw) {
                float res[4];
                batch4<true>(c, 8 * w, em, 4 * w, lane, stg[w], AH, AL, res);
                int valid = v - 4 * w; if (valid > 4) valid = 4;
                if (v == 1) {
                    if (tq == 0) {
                        #pragma unroll
                        for (int k = 0; k < 4; k++)
                            d_out[tg + 8 * k] = res[k];
                    }
                } else {
                    #pragma unroll
                    for (int k = 0; k < 4; k++)
                        if (tq < valid)
                            o[(4 * w + tq) * LBL + ((tg + 8 * k + 8 * tq) & 31)] = res[k];
                }
            }
            __syncthreads();
            c = o;
            o = (o == s2) ? s1 : s2;
        }
    }
}

// ---------------------------------------------------------------------------
// One graph node. Grid sized so ALL blocks are simultaneously resident.
// ---------------------------------------------------------------------------
extern "C" void kernel_launch(void* const* d_in, const int* in_sizes, int n_in,
                              void* d_out, int out_size)
{
    const float* emissions = (const float*)d_in[0];
    const float* trans     = (const float*)d_in[1];
    float* out = (float*)d_out;

    int n_nodes  = in_sizes[0] / LBL;
    int n_leaves = (n_nodes + 1) / 2;

    static int grid = 0;
    if (grid == 0) {
        int dev = 0, sms = 0, perSM = 0;
        cudaGetDevice(&dev);
        cudaDeviceGetAttribute(&sms, cudaDevAttrMultiProcessorCount, dev);
        cudaOccupancyMaxActiveBlocksPerMultiprocessor(
            &perSM, persistent_kernel, WPB * 32, 0);
        if (perSM < 1) perSM = 1;
        grid = sms * perSM;
        int maxSlabs = (n_leaves / 2) / 64;
        if (grid > maxSlabs) grid = maxSlabs;
        if (grid < 1) grid = 1;
    }

    persistent_kernel<<<grid, WPB * 32>>>(emissions, trans, out, n_leaves);
}